// round 1
// baseline (speedup 1.0000x reference)
#include <cuda_runtime.h>
#include <math_constants.h>

// Problem constants
#define SB   16          // batch
#define SS   577         // seq
#define DD   768         // hidden
#define HH   12          // heads
#define HD   64          // head dim
#define MTOT (SB*SS)     // 9232 rows for projection GEMMs

// Scratch (device globals: no allocation allowed)
__device__ float g_q[(size_t)SB*HH*SS*HD];
__device__ float g_k[(size_t)SB*HH*SS*HD];
__device__ float g_v[(size_t)SB*HH*SS*HD];
__device__ float g_bias[(size_t)HH*SS*SS];

// ---------------------------------------------------------------------------
// 1) Precompute bias[h][q][k] = table[idx[q*S+k]*H + h]
// ---------------------------------------------------------------------------
__global__ __launch_bounds__(256) void bias_kernel(const float* __restrict__ table,
                                                   const int* __restrict__ idx)
{
    int e = blockIdx.x * 256 + threadIdx.x;
    if (e >= SS * SS) return;
    int i = idx[e];
    #pragma unroll
    for (int h = 0; h < HH; h++)
        g_bias[(size_t)h * SS * SS + e] = table[i * HH + h];
}

// ---------------------------------------------------------------------------
// 2) Projection GEMM: out[b,h,s,d] = (X @ W + bias) * scale
//    blockIdx.z: 0 = Q (bias bq, scale 1/8), 1 = K (no bias), 2 = V (bias bv)
//    BM=64, BN=64, BK=16; 256 threads, 4x4 per thread.
// ---------------------------------------------------------------------------
__global__ __launch_bounds__(256) void proj_kernel(
    const float* __restrict__ X,
    const float* __restrict__ Wq, const float* __restrict__ bq,
    const float* __restrict__ Wk,
    const float* __restrict__ Wv, const float* __restrict__ bv)
{
    __shared__ float As[16][68];   // [k][m], padded (float4-aligned rows)
    __shared__ float Bs[16][64];   // [k][n]

    const int which = blockIdx.z;
    const float* W    = (which == 0) ? Wq : (which == 1) ? Wk : Wv;
    const float* bias = (which == 0) ? bq : (which == 2) ? bv : nullptr;
    const float scale = (which == 0) ? 0.125f : 1.0f;   // 1/sqrt(64)
    float* out = (which == 0) ? g_q : (which == 1) ? g_k : g_v;

    const int tid = threadIdx.x;
    const int tx = tid & 15, ty = tid >> 4;
    const int n0 = blockIdx.x * 64;
    const int m0 = blockIdx.y * 64;

    float acc[4][4] = {};

    for (int k0 = 0; k0 < DD; k0 += 16) {
        // load A tile (64 x 16), transposed into As[k][m]
        {
            int r = tid >> 2;           // 0..63 row within tile
            int c = (tid & 3) << 2;     // 0,4,8,12
            int m = m0 + r;
            float4 a = (m < MTOT) ? *(const float4*)&X[(size_t)m * DD + k0 + c]
                                  : make_float4(0.f, 0.f, 0.f, 0.f);
            As[c + 0][r] = a.x; As[c + 1][r] = a.y;
            As[c + 2][r] = a.z; As[c + 3][r] = a.w;
        }
        // load B tile (16 x 64)
        {
            int r = tid >> 4;
            int c = (tid & 15) << 2;
            *(float4*)&Bs[r][c] = *(const float4*)&W[(size_t)(k0 + r) * DD + n0 + c];
        }
        __syncthreads();
        #pragma unroll
        for (int kk = 0; kk < 16; kk++) {
            float4 a4 = *(float4*)&As[kk][ty << 2];
            float4 b4 = *(float4*)&Bs[kk][tx << 2];
            float av[4] = {a4.x, a4.y, a4.z, a4.w};
            float bv4[4] = {b4.x, b4.y, b4.z, b4.w};
            #pragma unroll
            for (int i = 0; i < 4; i++)
                #pragma unroll
                for (int j = 0; j < 4; j++)
                    acc[i][j] += av[i] * bv4[j];
        }
        __syncthreads();
    }

    // epilogue: this block's 64 cols are exactly one head (n0 % 64 == 0)
    const int h = n0 / HD;
    float badd[4];
    #pragma unroll
    for (int j = 0; j < 4; j++)
        badd[j] = bias ? bias[n0 + (tx << 2) + j] : 0.0f;

    #pragma unroll
    for (int i = 0; i < 4; i++) {
        int m = m0 + (ty << 2) + i;
        if (m >= MTOT) continue;
        int b = m / SS, s = m % SS;
        float4 o;
        o.x = (acc[i][0] + badd[0]) * scale;
        o.y = (acc[i][1] + badd[1]) * scale;
        o.z = (acc[i][2] + badd[2]) * scale;
        o.w = (acc[i][3] + badd[3]) * scale;
        *(float4*)&out[(((size_t)(b * HH + h) * SS + s) * HD) + (tx << 2)] = o;
    }
}

// ---------------------------------------------------------------------------
// 3) Flash attention: per (q-tile, b*h) block.
//    BQ=64, BK=32. 256 threads (16x16): each thread 4 q-rows;
//    S phase: 2 k-cols/thread; PV phase: 4 d-cols/thread.
// ---------------------------------------------------------------------------
__global__ __launch_bounds__(256) void attn_kernel(float* __restrict__ out)
{
    __shared__ float q_s[64][65];
    __shared__ float k_s[32][65];
    __shared__ float v_s[32][64];
    __shared__ float p_s[64][33];

    const int tid = threadIdx.x;
    const int tx = tid & 15, ty = tid >> 4;
    const int q0 = blockIdx.x * 64;
    const int bh = blockIdx.y;
    const int b = bh / HH, h = bh % HH;

    const float* qg = g_q + (size_t)bh * SS * HD;
    const float* kg = g_k + (size_t)bh * SS * HD;
    const float* vg = g_v + (size_t)bh * SS * HD;
    const float* biasg = g_bias + (size_t)h * SS * SS;

    // load Q tile (64 x 64) — zero-fill OOB rows
    for (int e = tid; e < 64 * 16; e += 256) {
        int r = e >> 4, c = (e & 15) << 2;
        int srow = q0 + r;
        float4 qv = (srow < SS) ? *(const float4*)&qg[(size_t)srow * HD + c]
                                : make_float4(0.f, 0.f, 0.f, 0.f);
        q_s[r][c] = qv.x; q_s[r][c + 1] = qv.y;
        q_s[r][c + 2] = qv.z; q_s[r][c + 3] = qv.w;
    }

    float m_r[4], l_r[4], o_acc[4][4];
    #pragma unroll
    for (int i = 0; i < 4; i++) {
        m_r[i] = -CUDART_INF_F; l_r[i] = 0.0f;
        #pragma unroll
        for (int j = 0; j < 4; j++) o_acc[i][j] = 0.0f;
    }

    const int NKT = (SS + 31) / 32;  // 19
    for (int jt = 0; jt < NKT; jt++) {
        const int j0 = jt * 32;
        __syncthreads();   // prev PV done (also covers initial Q load)

        // load K/V tiles (32 x 64)
        for (int e = tid; e < 32 * 16; e += 256) {
            int r = e >> 4, c = (e & 15) << 2;
            int srow = j0 + r;
            if (srow < SS) {
                float4 kv = *(const float4*)&kg[(size_t)srow * HD + c];
                k_s[r][c] = kv.x; k_s[r][c + 1] = kv.y;
                k_s[r][c + 2] = kv.z; k_s[r][c + 3] = kv.w;
                *(float4*)&v_s[r][c] = *(const float4*)&vg[(size_t)srow * HD + c];
            } else {
                k_s[r][c] = k_s[r][c + 1] = k_s[r][c + 2] = k_s[r][c + 3] = 0.0f;
                *(float4*)&v_s[r][c] = make_float4(0.f, 0.f, 0.f, 0.f);
            }
        }
        __syncthreads();

        // S = Q @ K^T (each thread: 4 q-rows x 2 k-cols)
        float sacc[4][2] = {};
        #pragma unroll 8
        for (int d = 0; d < 64; d++) {
            float a0 = q_s[(ty << 2) + 0][d];
            float a1 = q_s[(ty << 2) + 1][d];
            float a2 = q_s[(ty << 2) + 2][d];
            float a3 = q_s[(ty << 2) + 3][d];
            float c0 = k_s[(tx << 1) + 0][d];
            float c1 = k_s[(tx << 1) + 1][d];
            sacc[0][0] += a0 * c0; sacc[0][1] += a0 * c1;
            sacc[1][0] += a1 * c0; sacc[1][1] += a1 * c1;
            sacc[2][0] += a2 * c0; sacc[2][1] += a2 * c1;
            sacc[3][0] += a3 * c0; sacc[3][1] += a3 * c1;
        }

        // bias + mask
        #pragma unroll
        for (int i = 0; i < 4; i++) {
            int qrow = q0 + (ty << 2) + i;
            #pragma unroll
            for (int j = 0; j < 2; j++) {
                int kcol = j0 + (tx << 1) + j;
                if (kcol < SS) {
                    if (qrow < SS)
                        sacc[i][j] += __ldg(&biasg[(size_t)qrow * SS + kcol]);
                } else {
                    sacc[i][j] = -CUDART_INF_F;
                }
            }
        }

        // online softmax (row = 16 lanes within half-warp)
        #pragma unroll
        for (int i = 0; i < 4; i++) {
            float mx = fmaxf(sacc[i][0], sacc[i][1]);
            mx = fmaxf(mx, __shfl_xor_sync(0xffffffffu, mx, 1));
            mx = fmaxf(mx, __shfl_xor_sync(0xffffffffu, mx, 2));
            mx = fmaxf(mx, __shfl_xor_sync(0xffffffffu, mx, 4));
            mx = fmaxf(mx, __shfl_xor_sync(0xffffffffu, mx, 8));
            float m_new = fmaxf(m_r[i], mx);
            float corr = __expf(m_r[i] - m_new);   // first tile: exp(-inf)=0
            m_r[i] = m_new;
            float p0 = __expf(sacc[i][0] - m_new); // masked: exp(-inf)=0
            float p1 = __expf(sacc[i][1] - m_new);
            float rs = p0 + p1;
            rs += __shfl_xor_sync(0xffffffffu, rs, 1);
            rs += __shfl_xor_sync(0xffffffffu, rs, 2);
            rs += __shfl_xor_sync(0xffffffffu, rs, 4);
            rs += __shfl_xor_sync(0xffffffffu, rs, 8);
            l_r[i] = l_r[i] * corr + rs;
            #pragma unroll
            for (int j = 0; j < 4; j++) o_acc[i][j] *= corr;
            p_s[(ty << 2) + i][(tx << 1) + 0] = p0;
            p_s[(ty << 2) + i][(tx << 1) + 1] = p1;
        }
        __syncthreads();

        // O += P @ V (each thread: 4 q-rows x 4 d-cols)
        #pragma unroll 8
        for (int kk = 0; kk < 32; kk++) {
            float p0 = p_s[(ty << 2) + 0][kk];
            float p1 = p_s[(ty << 2) + 1][kk];
            float p2 = p_s[(ty << 2) + 2][kk];
            float p3 = p_s[(ty << 2) + 3][kk];
            float4 vv = *(float4*)&v_s[kk][tx << 2];
            o_acc[0][0] += p0 * vv.x; o_acc[0][1] += p0 * vv.y;
            o_acc[0][2] += p0 * vv.z; o_acc[0][3] += p0 * vv.w;
            o_acc[1][0] += p1 * vv.x; o_acc[1][1] += p1 * vv.y;
            o_acc[1][2] += p1 * vv.z; o_acc[1][3] += p1 * vv.w;
            o_acc[2][0] += p2 * vv.x; o_acc[2][1] += p2 * vv.y;
            o_acc[2][2] += p2 * vv.z; o_acc[2][3] += p2 * vv.w;
            o_acc[3][0] += p3 * vv.x; o_acc[3][1] += p3 * vv.y;
            o_acc[3][2] += p3 * vv.z; o_acc[3][3] += p3 * vv.w;
        }
    }

    // write out: [B,S,D] with d-col = h*64 + tx*4 + j
    #pragma unroll
    for (int i = 0; i < 4; i++) {
        int qrow = q0 + (ty << 2) + i;
        if (qrow >= SS) continue;
        float inv = 1.0f / l_r[i];
        float4 o;
        o.x = o_acc[i][0] * inv; o.y = o_acc[i][1] * inv;
        o.z = o_acc[i][2] * inv; o.w = o_acc[i][3] * inv;
        *(float4*)&out[((size_t)b * SS + qrow) * DD + h * HD + (tx << 2)] = o;
    }
}

// ---------------------------------------------------------------------------
extern "C" void kernel_launch(void* const* d_in, const int* in_sizes, int n_in,
                              void* d_out, int out_size)
{
    const float* X     = (const float*)d_in[0];
    const float* Wq    = (const float*)d_in[1];
    const float* bq    = (const float*)d_in[2];
    const float* Wk    = (const float*)d_in[3];
    const float* Wv    = (const float*)d_in[4];
    const float* bv    = (const float*)d_in[5];
    const float* table = (const float*)d_in[6];
    const int*   idx   = (const int*)d_in[7];
    float* out = (float*)d_out;

    // bias precompute
    bias_kernel<<<(SS * SS + 255) / 256, 256>>>(table, idx);

    // Q/K/V projections: grid (N/64, ceil(M/64), 3)
    dim3 pg(DD / 64, (MTOT + 63) / 64, 3);
    proj_kernel<<<pg, 256>>>(X, Wq, bq, Wk, Wv, bv);

    // flash attention: grid (q-tiles, B*H)
    dim3 ag((SS + 63) / 64, SB * HH);
    attn_kernel<<<ag, 256>>>(out);
}